// round 5
// baseline (speedup 1.0000x reference)
#include <cuda_runtime.h>
#include <cstdint>

// ----------------------------------------------------------------------------
// HashingDiscretizer — R5.
// Verified environment: keys arrive as int32, output is float32 concat
// [out_keys | out_vals] (2*nnz). feature_ids == arange(F) (runtime-verified,
// LUT fallback kept). 64-bit paths kept as guarded fallbacks.
// R5: 2 launches (probe folded into build), 8 elems/thread for gather MLP.
// ----------------------------------------------------------------------------

static constexpr int  LUT_SIZE = 65536;
static constexpr int  NBIN     = 63;
static constexpr int  ROW      = 72;        // 8 splitters + 8 leaves * 8
static constexpr int  MAX_F    = 8192;
static constexpr unsigned GOLDEN = 0x9E3779B9u;
static constexpr unsigned OUT_MASK_U = 0x3FFFFFu;        // (1<<22)-1

__device__ int g_is64 = 0;        // published by build_tables thread 0
__device__ int g_not_arange = 0;  // monotone 0->1 via atomicOr (deterministic)
__device__ unsigned short g_lut[LUT_SIZE];               // fallback LUT
__device__ __align__(32) float g_btree[MAX_F * ROW];

// ---- K1: fused width-probe + arange-check + LUT build + btree repack -------
// btree row (72 floats, 288B, 32B-aligned):
//   [0..7]   splitters bins[8j+7] (j<7), +INF pad
//   [8+8c+p] leaf c = bins[8c+p] (p<7), +INF pad
__global__ void build_tables(const void* __restrict__ fids,
                             const float* __restrict__ bins,
                             int F, int total_btree, int force64) {
    int t = blockIdx.x * blockDim.x + threadIdx.x;

    // local width probe (two cached word loads; uniform across threads)
    const int* fw = (const int*)fids;
    const bool is64 = force64 || (fw[1] == 0 && fw[3] == 0);
    if (t == 0) g_is64 = is64 ? 1 : 0;

    const long long* f64p = (const long long*)fids;
    const int*       f32p = (const int*)fids;

    if (t < LUT_SIZE) {
        if (t < F) {
            long long fv = is64 ? f64p[t] : (long long)f32p[t];
            if (fv != (long long)t) atomicOr(&g_not_arange, 1);
        }
        long long key = (long long)t;
        int lo = 0, hi = F;
        while (lo < hi) {
            int mid = (lo + hi) >> 1;
            long long fv = is64 ? f64p[mid] : (long long)f32p[mid];
            if (fv < key) lo = mid + 1; else hi = mid;
        }
        int idx = lo < (F - 1) ? lo : (F - 1);
        long long fv = is64 ? f64p[idx] : (long long)f32p[idx];
        unsigned short v = (unsigned short)(idx & 0x7FFF);
        if (fv == key) v |= 0x8000u;
        g_lut[t] = v;
    }
    if (t < total_btree) {
        int f = t / ROW;
        int j = t - f * ROW;
        const float INF = __int_as_float(0x7f800000);
        float v;
        if (j < 8) {
            v = (j < 7) ? __ldg(&bins[f * NBIN + 8 * j + 7]) : INF;
        } else {
            int q = j - 8, l = q >> 3, p = q & 7;
            v = (p < 7) ? __ldg(&bins[f * NBIN + 8 * l + p]) : INF;
        }
        g_btree[t] = v;
    }
}

// ---- per-element transform -------------------------------------------------
template <bool AR>
__device__ __forceinline__ void process_one(long long k, float v, int F,
                                            unsigned& okey, float& oval) {
    unsigned long long u = (unsigned long long)k;
    bool cal;
    int idx;
    if (AR) {
        cal = u < (unsigned long long)F;
        idx = (int)u;
    } else {
        if (u < (unsigned long long)LUT_SIZE) {
            unsigned short e = g_lut[u];
            cal = (e & 0x8000u) != 0;
            idx = (int)(e & 0x7FFFu);
        } else { cal = false; idx = 0; }
    }
    if (cal) {
        const float* nb = g_btree + idx * ROW;
        float4 s0 = *(const float4*)(nb);
        float4 s1 = *(const float4*)(nb + 4);
        int c = (s0.x < v) + (s0.y < v) + (s0.z < v) + (s0.w < v)
              + (s1.x < v) + (s1.y < v) + (s1.z < v) + (s1.w < v);
        const float* lf = nb + 8 + c * 8;
        float4 l0 = *(const float4*)(lf);
        float4 l1 = *(const float4*)(lf + 4);
        int bin = c * 8
              + (l0.x < v) + (l0.y < v) + (l0.z < v) + (l0.w < v)
              + (l1.x < v) + (l1.y < v) + (l1.z < v) + (l1.w < v);
        unsigned h = ((unsigned)u * GOLDEN + (unsigned)bin) * GOLDEN;
        okey = h & OUT_MASK_U;
        oval = 1.0f;
    } else {
        okey = (unsigned)(u & (unsigned long long)OUT_MASK_U);
        oval = v;
    }
}

template <bool IS64, bool AR>
__device__ __forceinline__ void run8(const void* __restrict__ keysv,
                                     const float* __restrict__ vals,
                                     int nnz, void* __restrict__ outv, int F) {
    int t = blockIdx.x * blockDim.x + threadIdx.x;
    int i0 = t * 8;
    if (i0 >= nnz) return;

    if (i0 + 7 < nnz) {
        long long k[8];
        if (IS64) {
            const long long* kp = (const long long*)keysv + i0;
            #pragma unroll
            for (int e = 0; e < 8; e += 2) {
                longlong2 a = __ldcs((const longlong2*)(kp + e));
                k[e] = a.x; k[e + 1] = a.y;
            }
        } else {
            const int* kp = (const int*)keysv + i0;
            int4 a = __ldcs((const int4*)kp);
            int4 b = __ldcs((const int4*)(kp + 4));
            k[0] = a.x; k[1] = a.y; k[2] = a.z; k[3] = a.w;
            k[4] = b.x; k[5] = b.y; k[6] = b.z; k[7] = b.w;
        }
        float v[8];
        {
            float4 a = __ldcs((const float4*)(vals + i0));
            float4 b = __ldcs((const float4*)(vals + i0 + 4));
            v[0] = a.x; v[1] = a.y; v[2] = a.z; v[3] = a.w;
            v[4] = b.x; v[5] = b.y; v[6] = b.z; v[7] = b.w;
        }

        unsigned ok[8]; float ov[8];
        #pragma unroll
        for (int e = 0; e < 8; e++)
            process_one<AR>(k[e], v[e], F, ok[e], ov[e]);

        if (IS64) {
            double* out = (double*)outv;
            #pragma unroll
            for (int e = 0; e < 8; e += 2)
                __stcs((double2*)(out + i0 + e),
                       make_double2((double)ok[e], (double)ok[e + 1]));
            if ((nnz & 1) == 0) {
                #pragma unroll
                for (int e = 0; e < 8; e += 2)
                    __stcs((double2*)(out + nnz + i0 + e),
                           make_double2((double)ov[e], (double)ov[e + 1]));
            } else {
                #pragma unroll
                for (int e = 0; e < 8; e++) out[nnz + i0 + e] = (double)ov[e];
            }
        } else {
            float* out = (float*)outv;
            __stcs((float4*)(out + i0),
                   make_float4((float)ok[0], (float)ok[1], (float)ok[2], (float)ok[3]));
            __stcs((float4*)(out + i0 + 4),
                   make_float4((float)ok[4], (float)ok[5], (float)ok[6], (float)ok[7]));
            if ((nnz & 3) == 0) {
                __stcs((float4*)(out + nnz + i0),
                       make_float4(ov[0], ov[1], ov[2], ov[3]));
                __stcs((float4*)(out + nnz + i0 + 4),
                       make_float4(ov[4], ov[5], ov[6], ov[7]));
            } else {
                #pragma unroll
                for (int e = 0; e < 8; e++) out[nnz + i0 + e] = ov[e];
            }
        }
    } else {
        for (int i = i0; i < nnz; i++) {
            long long k = IS64 ? ((const long long*)keysv)[i]
                               : (long long)((const int*)keysv)[i];
            unsigned ok; float ov;
            process_one<AR>(k, vals[i], F, ok, ov);
            if (IS64) {
                double* out = (double*)outv;
                out[i] = (double)ok; out[nnz + i] = (double)ov;
            } else {
                float* out = (float*)outv;
                out[i] = (float)ok;  out[nnz + i] = ov;
            }
        }
    }
}

__global__ void __launch_bounds__(256)
hashing_discretizer_kernel(const void* __restrict__ keys,
                           const float* __restrict__ vals,
                           int nnz, void* __restrict__ out, int F) {
    const bool is64 = (g_is64 != 0);
    const bool ar   = (g_not_arange == 0);
    if (is64) { if (ar) run8<true, true >(keys, vals, nnz, out, F);
                else    run8<true, false>(keys, vals, nnz, out, F); }
    else      { if (ar) run8<false, true >(keys, vals, nnz, out, F);
                else    run8<false, false>(keys, vals, nnz, out, F); }
}

extern "C" void kernel_launch(void* const* d_in, const int* in_sizes, int n_in,
                              void* d_out, int out_size) {
    // ---- classify inputs by element count (order-agnostic) ----
    long long s[16];
    int n = n_in < 16 ? n_in : 16;
    for (int i = 0; i < n; i++) s[i] = (long long)in_sizes[i];

    long long m1 = -1, m2 = -1;
    for (int i = 0; i < n; i++) {
        if (s[i] > m1) { m2 = m1; m1 = s[i]; }
        else if (s[i] > m2) { m2 = s[i]; }
    }

    int ik = -1, iv = -1;
    long long nnz_ll;
    int force64 = 0;
    if (m1 == m2) {
        for (int i = 0; i < n; i++)
            if (s[i] == m1) { if (ik < 0) ik = i; else if (iv < 0) iv = i; }
        nnz_ll = m1;
    } else {
        // int64 reinterpreted as 2x int32 words: keys = max, vals = max/2 entry
        for (int i = 0; i < n; i++) {
            if (s[i] == m1 && ik < 0) ik = i;
            else if (s[i] == m1 / 2 && iv < 0) iv = i;
        }
        nnz_ll = m1 / 2;
        force64 = 1;
    }
    if (iv < 0) iv = ik;

    int ia = -1, ib = -1;
    for (int i = 0; i < n; i++) {
        if (i == ik || i == iv) continue;
        if (ia < 0) ia = i; else if (ib < 0) ib = i;
    }
    if (ib < 0) ib = ia;
    int iF = (s[ia] <= s[ib]) ? ia : ib;   // feature_ids (smaller)
    int iB = (iF == ia) ? ib : ia;         // bin_vals

    int nnz = (int)nnz_ll;
    int F = (int)(force64 ? s[iF] / 2 : s[iF]);
    if (F > MAX_F) F = MAX_F;
    if (F < 1) F = 1;

    const void*  keys = d_in[ik];
    const float* vals = (const float*)d_in[iv];
    const void*  fids = d_in[iF];
    const float* bins = (const float*)d_in[iB];

    int total_btree = F * ROW;
    int build_n = (total_btree > LUT_SIZE) ? total_btree : LUT_SIZE;
    build_tables<<<(build_n + 255) / 256, 256>>>(fids, bins, F, total_btree,
                                                 force64);

    int nthreads = (nnz + 7) / 8;
    hashing_discretizer_kernel<<<(nthreads + 255) / 256, 256>>>(
        keys, vals, nnz, d_out, F);
}

// round 8
// speedup vs baseline: 1.1068x; 1.1068x over previous
#include <cuda_runtime.h>
#include <cstdint>

// ----------------------------------------------------------------------------
// HashingDiscretizer — R7 (R6 resubmitted after infra failure; unchanged).
// Verified env: keys int32, output f32 concat [out_keys | out_vals] (2*nnz),
// feature_ids == arange(F) (runtime-verified; LUT + 64-bit fallbacks kept).
// Pair-cooperative btree gather — 2 lanes split each 32B node, combine
// counts via shfl.xor -> 2 L1 wavefronts per calibrated element (was 4).
// ----------------------------------------------------------------------------

static constexpr int  LUT_SIZE = 65536;
static constexpr int  NBIN     = 63;
static constexpr int  ROW      = 72;        // 8 splitters + 8 leaves * 8
static constexpr int  MAX_F    = 8192;
static constexpr unsigned GOLDEN = 0x9E3779B9u;
static constexpr unsigned OUT_MASK_U = 0x3FFFFFu;        // (1<<22)-1

__device__ int g_is64 = 0;        // published by build_tables
__device__ int g_not_arange = 0;  // monotone 0->1 via atomicOr (deterministic)
__device__ unsigned short g_lut[LUT_SIZE];               // fallback LUT
__device__ __align__(32) float g_btree[MAX_F * ROW];

// ---- K1: fused width-probe + arange-check + LUT build + btree repack -------
// btree row (72 floats, 288B, 32B-aligned):
//   [0..7]   splitters bins[8j+7] (j<7), +INF pad
//   [8+8c+p] leaf c = bins[8c+p] (p<7), +INF pad
__global__ void build_tables(const void* __restrict__ fids,
                             const float* __restrict__ bins,
                             int F, int total_btree, int force64) {
    int t = blockIdx.x * blockDim.x + threadIdx.x;

    const int* fw = (const int*)fids;
    const bool is64 = force64 || (fw[1] == 0 && fw[3] == 0);
    if (t == 0) g_is64 = is64 ? 1 : 0;

    const long long* f64p = (const long long*)fids;
    const int*       f32p = (const int*)fids;

    if (t < LUT_SIZE) {
        if (t < F) {
            long long fv = is64 ? f64p[t] : (long long)f32p[t];
            if (fv != (long long)t) atomicOr(&g_not_arange, 1);
        }
        long long key = (long long)t;
        int lo = 0, hi = F;
        while (lo < hi) {
            int mid = (lo + hi) >> 1;
            long long fv = is64 ? f64p[mid] : (long long)f32p[mid];
            if (fv < key) lo = mid + 1; else hi = mid;
        }
        int idx = lo < (F - 1) ? lo : (F - 1);
        long long fv = is64 ? f64p[idx] : (long long)f32p[idx];
        unsigned short v = (unsigned short)(idx & 0x7FFF);
        if (fv == key) v |= 0x8000u;
        g_lut[t] = v;
    }
    if (t < total_btree) {
        int f = t / ROW;
        int j = t - f * ROW;
        const float INF = __int_as_float(0x7f800000);
        float v;
        if (j < 8) {
            v = (j < 7) ? __ldg(&bins[f * NBIN + 8 * j + 7]) : INF;
        } else {
            int q = j - 8, l = q >> 3, p = q & 7;
            v = (p < 7) ? __ldg(&bins[f * NBIN + 8 * l + p]) : INF;
        }
        g_btree[t] = v;
    }
}

// ---- generic per-element path (fallback configs) ---------------------------
template <bool AR>
__device__ __forceinline__ void process_one(long long k, float v, int F,
                                            unsigned& okey, float& oval) {
    unsigned long long u = (unsigned long long)k;
    bool cal; int idx;
    if (AR) { cal = u < (unsigned long long)F; idx = (int)u; }
    else {
        if (u < (unsigned long long)LUT_SIZE) {
            unsigned short e = g_lut[u];
            cal = (e & 0x8000u) != 0; idx = (int)(e & 0x7FFFu);
        } else { cal = false; idx = 0; }
    }
    if (cal) {
        const float* nb = g_btree + idx * ROW;
        float4 s0 = *(const float4*)(nb);
        float4 s1 = *(const float4*)(nb + 4);
        int c = (s0.x < v) + (s0.y < v) + (s0.z < v) + (s0.w < v)
              + (s1.x < v) + (s1.y < v) + (s1.z < v) + (s1.w < v);
        const float* lf = nb + 8 + c * 8;
        float4 l0 = *(const float4*)(lf);
        float4 l1 = *(const float4*)(lf + 4);
        int bin = c * 8
              + (l0.x < v) + (l0.y < v) + (l0.z < v) + (l0.w < v)
              + (l1.x < v) + (l1.y < v) + (l1.z < v) + (l1.w < v);
        unsigned h = ((unsigned)u * GOLDEN + (unsigned)bin) * GOLDEN;
        okey = h & OUT_MASK_U; oval = 1.0f;
    } else {
        okey = (unsigned)(u & (unsigned long long)OUT_MASK_U);
        oval = v;
    }
}

template <bool IS64, bool AR>
__device__ __forceinline__ void run4_fallback(const void* __restrict__ keysv,
                                              const float* __restrict__ vals,
                                              int nnz, void* __restrict__ outv,
                                              int F) {
    int t = blockIdx.x * blockDim.x + threadIdx.x;
    int i0 = t * 4;
    if (i0 >= nnz) return;
    int iend = (i0 + 4 < nnz) ? i0 + 4 : nnz;
    for (int i = i0; i < iend; i++) {
        long long k = IS64 ? ((const long long*)keysv)[i]
                           : (long long)((const int*)keysv)[i];
        unsigned ok; float ov;
        process_one<AR>(k, vals[i], F, ok, ov);
        if (IS64) {
            double* out = (double*)outv;
            out[i] = (double)ok; out[nnz + i] = (double)ov;
        } else {
            float* out = (float*)outv;
            out[i] = (float)ok;  out[nnz + i] = ov;
        }
    }
}

// ---- hot path: int32 keys, f32 out, arange feature table -------------------
// Warp handles 64 consecutive elements: 16 lane-pairs x 4 elements each.
// Within a pair, lane half h loads the h-th 16B of each 32B btree node and
// partial counts combine via shfl.xor(1): 1 wavefront per node per element.
__device__ __forceinline__ void run_pair32(const int* __restrict__ keys,
                                           const float* __restrict__ vals,
                                           int nnz, float* __restrict__ out,
                                           int F) {
    int gt     = blockIdx.x * blockDim.x + threadIdx.x;
    int warpId = gt >> 5;
    int lane   = threadIdx.x & 31;
    int half   = lane & 1;           // which 16B half of the node
    int pair   = lane >> 1;          // 0..15
    long long warpBase = (long long)warpId * 64;
    if (warpBase >= nnz) return;

    if (warpBase + 64 <= nnz) {
        int base = (int)warpBase + pair * 4;
        int4   kk = __ldcs((const int4*)(keys + base));
        float4 vv = __ldcs((const float4*)(vals + base));
        int   k[4] = {kk.x, kk.y, kk.z, kk.w};
        float v[4] = {vv.x, vv.y, vv.z, vv.w};
        float ok[4], ov[4];

        #pragma unroll
        for (int j = 0; j < 4; j++) {
            unsigned u = (unsigned)k[j];
            bool cal = u < (unsigned)F;
            float vj = v[j];
            const float4* nb = (const float4*)(g_btree + (cal ? (int)u : 0) * ROW);
            // level 1: pair covers 7 splitters (+INF pad), 1 wavefront
            float4 s = nb[half];
            int cnt = cal ? ((s.x < vj) + (s.y < vj) + (s.z < vj) + (s.w < vj))
                          : 0;
            int c = cnt + __shfl_xor_sync(0xFFFFFFFFu, cnt, 1);
            // level 2: leaf c (32B, 32B-aligned), 1 wavefront
            float4 l = nb[2 + c * 2 + half];
            int cnt2 = cal ? ((l.x < vj) + (l.y < vj) + (l.z < vj) + (l.w < vj))
                           : 0;
            int bin = c * 8 + cnt2 + __shfl_xor_sync(0xFFFFFFFFu, cnt2, 1);

            unsigned h = (u * GOLDEN + (unsigned)bin) * GOLDEN;
            ok[j] = cal ? (float)(h & OUT_MASK_U) : (float)(u & OUT_MASK_U);
            ov[j] = cal ? 1.0f : vj;
        }
        if (half == 0)
            __stcs((float4*)(out + base), make_float4(ok[0], ok[1], ok[2], ok[3]));
        else
            __stcs((float4*)(out + nnz + base), make_float4(ov[0], ov[1], ov[2], ov[3]));
    } else {
        // tail warp: plain per-lane scalar path (no shuffles)
        for (long long i = warpBase + lane; i < nnz; i += 32) {
            unsigned ok; float ov;
            process_one<true>((long long)keys[i], vals[i], F, ok, ov);
            out[i] = (float)ok;
            out[nnz + i] = ov;
        }
    }
}

__global__ void __launch_bounds__(256)
hashing_discretizer_kernel(const void* __restrict__ keys,
                           const float* __restrict__ vals,
                           int nnz, void* __restrict__ out, int F) {
    const bool is64 = (g_is64 != 0);
    const bool ar   = (g_not_arange == 0);
    if (!is64 && ar) {
        run_pair32((const int*)keys, (const float*)vals, nnz, (float*)out, F);
    } else if (is64) {
        if (ar) run4_fallback<true, true >(keys, vals, nnz, out, F);
        else    run4_fallback<true, false>(keys, vals, nnz, out, F);
    } else {
        run4_fallback<false, false>(keys, vals, nnz, out, F);
    }
}

extern "C" void kernel_launch(void* const* d_in, const int* in_sizes, int n_in,
                              void* d_out, int out_size) {
    // ---- classify inputs by element count (order-agnostic) ----
    long long s[16];
    int n = n_in < 16 ? n_in : 16;
    for (int i = 0; i < n; i++) s[i] = (long long)in_sizes[i];

    long long m1 = -1, m2 = -1;
    for (int i = 0; i < n; i++) {
        if (s[i] > m1) { m2 = m1; m1 = s[i]; }
        else if (s[i] > m2) { m2 = s[i]; }
    }

    int ik = -1, iv = -1;
    long long nnz_ll;
    int force64 = 0;
    if (m1 == m2) {
        for (int i = 0; i < n; i++)
            if (s[i] == m1) { if (ik < 0) ik = i; else if (iv < 0) iv = i; }
        nnz_ll = m1;
    } else {
        for (int i = 0; i < n; i++) {
            if (s[i] == m1 && ik < 0) ik = i;
            else if (s[i] == m1 / 2 && iv < 0) iv = i;
        }
        nnz_ll = m1 / 2;
        force64 = 1;
    }
    if (iv < 0) iv = ik;

    int ia = -1, ib = -1;
    for (int i = 0; i < n; i++) {
        if (i == ik || i == iv) continue;
        if (ia < 0) ia = i; else if (ib < 0) ib = i;
    }
    if (ib < 0) ib = ia;
    int iF = (s[ia] <= s[ib]) ? ia : ib;   // feature_ids (smaller)
    int iB = (iF == ia) ? ib : ia;         // bin_vals

    int nnz = (int)nnz_ll;
    int F = (int)(force64 ? s[iF] / 2 : s[iF]);
    if (F > MAX_F) F = MAX_F;
    if (F < 1) F = 1;

    const void*  keys = d_in[ik];
    const float* vals = (const float*)d_in[iv];
    const void*  fids = d_in[iF];
    const float* bins = (const float*)d_in[iB];

    int total_btree = F * ROW;
    int build_n = (total_btree > LUT_SIZE) ? total_btree : LUT_SIZE;
    build_tables<<<(build_n + 255) / 256, 256>>>(fids, bins, F, total_btree,
                                                 force64);

    // threads: hot path needs ceil(nnz/64) warps; fallback (4/thread) needs
    // fewer and self-guards, so size for the hot path.
    long long warps = ((long long)nnz + 63) / 64;
    long long threads = warps * 32;
    int blocks = (int)((threads + 255) / 256);
    if (blocks < 1) blocks = 1;
    hashing_discretizer_kernel<<<blocks, 256>>>(keys, vals, nnz, d_out, F);
}